// round 1
// baseline (speedup 1.0000x reference)
#include <cuda_runtime.h>
#include <cstdint>

// TinyMoE: B=4,S=2048 -> N=8192 tokens, H=1024, E=8, top-2 routing.
// out[n,h] = sum_k w_k * (x[n] @ W_{e_k})[h] + sum_k w_k * p_k
//
// Stage 1: router (logits, softmax, top2) + bucket (token, weight, slot) per expert
// Stage 2: per-expert gathered SGEMM (128x128x8 tiles, packed fma.rn.f32x2 core),
//          writes weighted rows into g_buf[slot] (slot = rank k of expert for that token)
// Stage 3: combine out = buf0 + buf1 + C_n

#define H      1024
#define NTOK   8192
#define NEXP   8
#define MAXPE  16384   // worst case: all (token,k) pairs to one expert
#define BM     128
#define BN     128
#define BK     8

__device__ int   g_count[NEXP];
__device__ int   g_tok [NEXP][MAXPE];
__device__ float g_wt  [NEXP][MAXPE];
__device__ int   g_slot[NEXP][MAXPE];
__device__ float g_C   [NTOK];
__device__ float g_buf [2][(size_t)NTOK * H];   // 64 MB scratch

// ---------------------------------------------------------------- helpers
__device__ __forceinline__ unsigned long long pack2(float lo, float hi) {
    unsigned long long r;
    asm("mov.b64 %0, {%1, %2};" : "=l"(r) : "f"(lo), "f"(hi));
    return r;
}
__device__ __forceinline__ void fma2(unsigned long long& d,
                                     unsigned long long a,
                                     unsigned long long b) {
    asm("fma.rn.f32x2 %0, %1, %2, %0;" : "+l"(d) : "l"(a), "l"(b));
}
__device__ __forceinline__ float2 unpack2(unsigned long long v) {
    float2 f;
    asm("mov.b64 {%0, %1}, %2;" : "=f"(f.x), "=f"(f.y) : "l"(v));
    return f;
}

// ---------------------------------------------------------------- stage 0
__global__ void reset_kernel() {
    if (threadIdx.x < NEXP) g_count[threadIdx.x] = 0;
}

// ---------------------------------------------------------------- stage 1
// 256 threads = 8 warps, one warp per token. router_w (32KB) cached in smem.
__global__ __launch_bounds__(256) void router_kernel(const float* __restrict__ x,
                                                     const float* __restrict__ rw) {
    __shared__ float s_rw[NEXP * H];
    int t = threadIdx.x;
    {
        const float4* rw4 = (const float4*)rw;
        float4* s4 = (float4*)s_rw;
        #pragma unroll
        for (int i = 0; i < (NEXP * H / 4) / 256; i++)
            s4[t + i * 256] = rw4[t + i * 256];
    }
    __syncthreads();

    int wid = t >> 5, lane = t & 31;
    int n = blockIdx.x * 8 + wid;
    const float* xr = x + (size_t)n * H;

    float acc[NEXP];
    #pragma unroll
    for (int e = 0; e < NEXP; e++) acc[e] = 0.f;

    #pragma unroll 8
    for (int i = 0; i < H / 32; i++) {
        float xv = xr[i * 32 + lane];
        #pragma unroll
        for (int e = 0; e < NEXP; e++)
            acc[e] += xv * s_rw[e * H + i * 32 + lane];
    }
    #pragma unroll
    for (int e = 0; e < NEXP; e++) {
        #pragma unroll
        for (int off = 16; off > 0; off >>= 1)
            acc[e] += __shfl_xor_sync(0xffffffffu, acc[e], off);
    }

    if (lane == 0) {
        float m = acc[0];
        #pragma unroll
        for (int e = 1; e < NEXP; e++) m = fmaxf(m, acc[e]);
        float p[NEXP]; float s = 0.f;
        #pragma unroll
        for (int e = 0; e < NEXP; e++) { p[e] = expf(acc[e] - m); s += p[e]; }
        float inv = 1.f / s;

        // top-2 with jax tie-break (lowest index wins on ties -> strict >)
        int b1 = 0; float v1 = acc[0];
        #pragma unroll
        for (int e = 1; e < NEXP; e++) if (acc[e] > v1) { v1 = acc[e]; b1 = e; }
        int b2 = -1; float v2 = -3.4e38f;
        #pragma unroll
        for (int e = 0; e < NEXP; e++)
            if (e != b1 && acc[e] > v2) { v2 = acc[e]; b2 = e; }

        float p0 = p[b1] * inv, p1 = p[b2] * inv;
        float ws = 1.f / (p0 + p1 + 1e-6f);
        float w0 = p0 * ws, w1 = p1 * ws;

        g_C[n] = w0 * p0 + w1 * p1;

        int pos0 = atomicAdd(&g_count[b1], 1);
        g_tok[b1][pos0] = n; g_wt[b1][pos0] = w0; g_slot[b1][pos0] = 0;
        int pos1 = atomicAdd(&g_count[b2], 1);
        g_tok[b2][pos1] = n; g_wt[b2][pos1] = w1; g_slot[b2][pos1] = 1;
    }
}

// ---------------------------------------------------------------- stage 2
// Gathered SGEMM: C[i, :] = wt_i * (x[tok_i] @ W_e), 128x128 tile per block,
// 256 threads, 8x8 per-thread microtile as 8x4 packed f32x2 accumulators.
// A is stored duplicated ({v,v}) in smem so the inner loop needs no packing.
__global__ __launch_bounds__(256, 2) void expert_gemm(const float* __restrict__ x,
                                                      const float* __restrict__ Wall) {
    int e   = blockIdx.z;
    int cnt = g_count[e];
    int m0  = blockIdx.x * BM;
    if (m0 >= cnt) return;
    int n0  = blockIdx.y * BN;
    const float* W = Wall + (size_t)e * H * H + n0;

    __shared__ int   s_tok[BM];
    __shared__ float s_wt [BM];
    __shared__ int   s_slot[BM];
    __shared__ __align__(16) unsigned long long As[BK][BM + 2]; // duplicated A, padded
    __shared__ __align__(16) float Bs[BK][BN];

    int t = threadIdx.x;
    if (t < BM) {
        int i = m0 + t;
        int src = (i < cnt) ? i : (cnt - 1);   // cnt >= 1 here
        s_tok[t]  = g_tok[e][src];
        s_wt[t]   = g_wt[e][src];
        s_slot[t] = g_slot[e][src];
    }
    __syncthreads();

    int arow = t >> 1, akq = t & 1;                       // A: 2 threads per row
    const float* ap = x + (size_t)s_tok[arow] * H + akq * 4;
    int brow = t >> 5, bcol = (t & 31) * 4;               // B: 32 threads per k-row
    const float* bp = W + (size_t)brow * H + bcol;

    int tx = t & 15, ty = t >> 4;

    unsigned long long acc[8][4];
    #pragma unroll
    for (int i = 0; i < 8; i++)
        #pragma unroll
        for (int j = 0; j < 4; j++) acc[i][j] = 0ull;

    for (int k0 = 0; k0 < H; k0 += BK) {
        float4 av = *(const float4*)(ap + k0);
        float4 bv = *(const float4*)(bp + (size_t)k0 * H);
        As[akq * 4 + 0][arow] = pack2(av.x, av.x);
        As[akq * 4 + 1][arow] = pack2(av.y, av.y);
        As[akq * 4 + 2][arow] = pack2(av.z, av.z);
        As[akq * 4 + 3][arow] = pack2(av.w, av.w);
        *(float4*)&Bs[brow][bcol] = bv;
        __syncthreads();

        #pragma unroll
        for (int kk = 0; kk < BK; kk++) {
            ulonglong2 a01 = *(const ulonglong2*)&As[kk][ty * 8 + 0];
            ulonglong2 a23 = *(const ulonglong2*)&As[kk][ty * 8 + 2];
            ulonglong2 a45 = *(const ulonglong2*)&As[kk][ty * 8 + 4];
            ulonglong2 a67 = *(const ulonglong2*)&As[kk][ty * 8 + 6];
            ulonglong2 b01 = *(const ulonglong2*)&Bs[kk][tx * 8 + 0];
            ulonglong2 b23 = *(const ulonglong2*)&Bs[kk][tx * 8 + 4];
            unsigned long long a_[8] = {a01.x, a01.y, a23.x, a23.y,
                                        a45.x, a45.y, a67.x, a67.y};
            unsigned long long b_[4] = {b01.x, b01.y, b23.x, b23.y};
            #pragma unroll
            for (int i = 0; i < 8; i++)
                #pragma unroll
                for (int j = 0; j < 4; j++)
                    fma2(acc[i][j], a_[i], b_[j]);
        }
        __syncthreads();
    }

    // epilogue: scale by routing weight, scatter to buf[slot][token]
    #pragma unroll
    for (int i = 0; i < 8; i++) {
        int r = ty * 8 + i;
        if (m0 + r < cnt) {
            float wt = s_wt[r];
            float* dst = g_buf[s_slot[r]] + (size_t)s_tok[r] * H + n0 + tx * 8;
            float2 f0 = unpack2(acc[i][0]);
            float2 f1 = unpack2(acc[i][1]);
            float2 f2 = unpack2(acc[i][2]);
            float2 f3 = unpack2(acc[i][3]);
            float4 o0 = make_float4(f0.x * wt, f0.y * wt, f1.x * wt, f1.y * wt);
            float4 o1 = make_float4(f2.x * wt, f2.y * wt, f3.x * wt, f3.y * wt);
            *(float4*)dst       = o0;
            *(float4*)(dst + 4) = o1;
        }
    }
}

// ---------------------------------------------------------------- stage 3
__global__ __launch_bounds__(256) void combine_kernel(float* __restrict__ out) {
    size_t idx = (size_t)blockIdx.x * 256 + threadIdx.x;  // float4 index
    int n = (int)(idx >> 8);                              // idx*4 / 1024
    float4 a = ((const float4*)g_buf[0])[idx];
    float4 b = ((const float4*)g_buf[1])[idx];
    float  c = g_C[n];
    float4 o;
    o.x = a.x + b.x + c;
    o.y = a.y + b.y + c;
    o.z = a.z + b.z + c;
    o.w = a.w + b.w + c;
    ((float4*)out)[idx] = o;
}

// ---------------------------------------------------------------- launch
extern "C" void kernel_launch(void* const* d_in, const int* in_sizes, int n_in,
                              void* d_out, int out_size) {
    const float* x  = (const float*)d_in[0];   // [8192, 1024]
    const float* rw = (const float*)d_in[1];   // [8, 1024]
    const float* W  = (const float*)d_in[2];   // [8, 1024, 1024]
    float* out = (float*)d_out;                // [8192, 1024]

    reset_kernel<<<1, 32>>>();
    router_kernel<<<NTOK / 8, 256>>>(x, rw);
    dim3 g(MAXPE / BM, H / BN, NEXP);
    expert_gemm<<<g, 256>>>(x, W);
    combine_kernel<<<(NTOK * H / 4) / 256, 256>>>(out);
}

// round 3
// speedup vs baseline: 2.6592x; 2.6592x over previous
#include <cuda_runtime.h>
#include <cuda_bf16.h>
#include <cstdint>

// TinyMoE: N=8192 tokens, H=1024, E=8, top-2.
// out[n,h] = sum_k w_k * (x[n] @ W_{e_k})[h] + C_n
//
// R3: HMMA (mma.sync bf16) expert GEMM — base-PTX tensor cores (tcgen05 is
// unavailable: harness emits compute_103 base PTX). fp32 accuracy recovered
// via 3-term bf16 split folded into K'=3072 concatenated operands:
//   x' = [xh | xh | xl],  w'^T = [wh | wl | wh]  ->  x'.w' = xh.wh+xh.wl+xl.wh

#define H      1024
#define KC     3072          // concatenated K
#define NTOK   8192
#define NEXP   8
#define MAXPE  16384
#define BM     128
#define BN     128
#define BKH    64            // bf16 per k-slab (128 bytes)
#define KITER  (KC / BKH)    // 48
#define PSTAGE 3

__device__ int   g_count[NEXP];
__device__ int   g_tok [NEXP][MAXPE];
__device__ float g_wt  [NEXP][MAXPE];
__device__ int   g_slot[NEXP][MAXPE];
__device__ float g_C   [NTOK];
__device__ float g_buf [2][(size_t)NTOK * H];
__device__ __nv_bfloat16 g_xc[(size_t)NTOK * KC];            // [n][3072]
__device__ __nv_bfloat16 g_wc[(size_t)NEXP * H * KC];        // [e][out][3072]

// ------------------------------------------------------------------ utils
__device__ __forceinline__ uint32_t smem_u32(const void* p) {
    uint32_t a;
    asm("{ .reg .u64 t; cvta.to.shared.u64 t, %1; cvt.u32.u64 %0, t; }"
        : "=r"(a) : "l"(p));
    return a;
}
#define SWZ(o) ((o) ^ ((((uint32_t)(o)) >> 3) & 0x70))

__device__ __forceinline__ void cp16(uint32_t d, const void* s) {
    asm volatile("cp.async.cg.shared.global [%0], [%1], 16;" :: "r"(d), "l"(s));
}
#define CP_COMMIT()  asm volatile("cp.async.commit_group;" ::: "memory")
#define CP_WAIT1()   asm volatile("cp.async.wait_group 1;" ::: "memory")

__device__ __forceinline__ void ldm4(uint32_t a, uint32_t& r0, uint32_t& r1,
                                     uint32_t& r2, uint32_t& r3) {
    asm volatile("ldmatrix.sync.aligned.m8n8.x4.shared.b16 {%0,%1,%2,%3}, [%4];"
                 : "=r"(r0), "=r"(r1), "=r"(r2), "=r"(r3) : "r"(a));
}
__device__ __forceinline__ void mma16816(float* c, const uint32_t* a,
                                         uint32_t b0, uint32_t b1) {
    asm volatile(
        "mma.sync.aligned.m16n8k16.row.col.f32.bf16.bf16.f32 "
        "{%0,%1,%2,%3}, {%4,%5,%6,%7}, {%8,%9}, {%0,%1,%2,%3};"
        : "+f"(c[0]), "+f"(c[1]), "+f"(c[2]), "+f"(c[3])
        : "r"(a[0]), "r"(a[1]), "r"(a[2]), "r"(a[3]), "r"(b0), "r"(b1));
}

// ------------------------------------------------------------------ stage 0
__global__ void reset_kernel() {
    if (threadIdx.x < NEXP) g_count[threadIdx.x] = 0;
}

// ------------------------------------------------------------------ convert x
__global__ __launch_bounds__(256) void convert_x(const float* __restrict__ x) {
    size_t i = ((size_t)blockIdx.x * 256 + threadIdx.x) * 4;
    int n = (int)(i >> 10), col = (int)(i & 1023);
    float4 v = *(const float4*)(x + i);
    __nv_bfloat16 h0 = __float2bfloat16(v.x), h1 = __float2bfloat16(v.y);
    __nv_bfloat16 h2 = __float2bfloat16(v.z), h3 = __float2bfloat16(v.w);
    __nv_bfloat16 l0 = __float2bfloat16(v.x - __bfloat162float(h0));
    __nv_bfloat16 l1 = __float2bfloat16(v.y - __bfloat162float(h1));
    __nv_bfloat16 l2 = __float2bfloat16(v.z - __bfloat162float(h2));
    __nv_bfloat16 l3 = __float2bfloat16(v.w - __bfloat162float(h3));
    __nv_bfloat162 hA = __halves2bfloat162(h0, h1), hB = __halves2bfloat162(h2, h3);
    __nv_bfloat162 lA = __halves2bfloat162(l0, l1), lB = __halves2bfloat162(l2, l3);
    __nv_bfloat16* base = g_xc + (size_t)n * KC + col;
    ((__nv_bfloat162*)(base        ))[0] = hA; ((__nv_bfloat162*)(base        ))[1] = hB;
    ((__nv_bfloat162*)(base + 1024 ))[0] = hA; ((__nv_bfloat162*)(base + 1024 ))[1] = hB;
    ((__nv_bfloat162*)(base + 2048 ))[0] = lA; ((__nv_bfloat162*)(base + 2048 ))[1] = lB;
}

// ------------------------------------------------------------------ convert+transpose W
// W[e][in][out] fp32 -> g_wc[e][out][{wh|wl|wh}] bf16
__global__ __launch_bounds__(256) void convert_w(const float* __restrict__ W) {
    __shared__ float tile[32][33];
    int e = blockIdx.z, h0 = blockIdx.x * 32, o0 = blockIdx.y * 32;
    int tx = threadIdx.x & 31, ty = threadIdx.x >> 5;
    const float* src = W + ((size_t)e * H + h0) * H + o0;
    #pragma unroll
    for (int r = ty; r < 32; r += 8)
        tile[r][tx] = src[(size_t)r * H + tx];
    __syncthreads();
    #pragma unroll
    for (int r = ty; r < 32; r += 8) {
        float v = tile[tx][r];   // W[h0+tx][o0+r]
        __nv_bfloat16 hi = __float2bfloat16(v);
        __nv_bfloat16 lo = __float2bfloat16(v - __bfloat162float(hi));
        __nv_bfloat16* base = g_wc + ((size_t)e * H + o0 + r) * KC + h0 + tx;
        base[0]    = hi;
        base[1024] = lo;
        base[2048] = hi;
    }
}

// ------------------------------------------------------------------ router
__global__ __launch_bounds__(256) void router_kernel(const float* __restrict__ x,
                                                     const float* __restrict__ rw) {
    __shared__ float s_rw[NEXP * H];
    int t = threadIdx.x;
    {
        const float4* rw4 = (const float4*)rw;
        float4* s4 = (float4*)s_rw;
        #pragma unroll
        for (int i = 0; i < (NEXP * H / 4) / 256; i++)
            s4[t + i * 256] = rw4[t + i * 256];
    }
    __syncthreads();

    int wid = t >> 5, lane = t & 31;
    int n = blockIdx.x * 8 + wid;
    const float* xr = x + (size_t)n * H;

    float acc[NEXP];
    #pragma unroll
    for (int e = 0; e < NEXP; e++) acc[e] = 0.f;
    #pragma unroll 8
    for (int i = 0; i < H / 32; i++) {
        float xv = xr[i * 32 + lane];
        #pragma unroll
        for (int e = 0; e < NEXP; e++) acc[e] += xv * s_rw[e * H + i * 32 + lane];
    }
    #pragma unroll
    for (int e = 0; e < NEXP; e++) {
        #pragma unroll
        for (int off = 16; off > 0; off >>= 1)
            acc[e] += __shfl_xor_sync(0xffffffffu, acc[e], off);
    }
    if (lane == 0) {
        float m = acc[0];
        #pragma unroll
        for (int e = 1; e < NEXP; e++) m = fmaxf(m, acc[e]);
        float p[NEXP]; float s = 0.f;
        #pragma unroll
        for (int e = 0; e < NEXP; e++) { p[e] = expf(acc[e] - m); s += p[e]; }
        float inv = 1.f / s;
        int b1 = 0; float v1 = acc[0];
        #pragma unroll
        for (int e = 1; e < NEXP; e++) if (acc[e] > v1) { v1 = acc[e]; b1 = e; }
        int b2 = -1; float v2 = -3.4e38f;
        #pragma unroll
        for (int e = 0; e < NEXP; e++)
            if (e != b1 && acc[e] > v2) { v2 = acc[e]; b2 = e; }
        float p0 = p[b1] * inv, p1 = p[b2] * inv;
        float ws = 1.f / (p0 + p1 + 1e-6f);
        float w0 = p0 * ws, w1 = p1 * ws;
        g_C[n] = w0 * p0 + w1 * p1;
        int pos0 = atomicAdd(&g_count[b1], 1);
        g_tok[b1][pos0] = n; g_wt[b1][pos0] = w0; g_slot[b1][pos0] = 0;
        int pos1 = atomicAdd(&g_count[b2], 1);
        g_tok[b2][pos1] = n; g_wt[b2][pos1] = w1; g_slot[b2][pos1] = 1;
    }
}

// ------------------------------------------------------------------ HMMA GEMM
// 128x128 tile, K'=3072, 3-stage cp.async pipeline, 8 warps (2x4), warp 64x32.
#define STAGE_BYTES 32768                       // A 16KB + B 16KB
#define SMEM_BYTES  (PSTAGE * STAGE_BYTES)      // 98304

__global__ __launch_bounds__(256, 2) void expert_gemm() {
    extern __shared__ char smem[];
    __shared__ int   s_tok[BM];
    __shared__ float s_wt [BM];
    __shared__ int   s_slot[BM];

    int e = blockIdx.z;
    int cnt = g_count[e];
    int m0 = blockIdx.x * BM;
    if (m0 >= cnt) return;
    int n0 = blockIdx.y * BN;

    int t = threadIdx.x;
    if (t < BM) {
        int src = min(m0 + t, cnt - 1);
        s_tok[t]  = g_tok[e][src];
        s_wt[t]   = g_wt[e][src];
        s_slot[t] = g_slot[e][src];
    }
    __syncthreads();

    const uint32_t sb = smem_u32(smem);

    // ---- loader: thread t covers rows lr+32*i (i<4), 16B chunk lc
    const int lr = t >> 3, lc = t & 7;
    const __nv_bfloat16* aptr[4];
    const __nv_bfloat16* bptr[4];
    #pragma unroll
    for (int i = 0; i < 4; i++) {
        int r = lr + 32 * i;
        aptr[i] = g_xc + (size_t)s_tok[r] * KC + lc * 8;
        bptr[i] = g_wc + ((size_t)e * H + n0 + r) * KC + lc * 8;
    }
    const uint32_t dsw = SWZ(lr * 128 + lc * 16);   // same swizzled offset all stages

    #define ISSUE(it) do {                                                   \
        int _st = (it) % PSTAGE; int _k0 = (it) * BKH;                       \
        uint32_t _ab = sb + _st * STAGE_BYTES;                               \
        uint32_t _bb = _ab + 16384;                                          \
        _Pragma("unroll")                                                    \
        for (int _i = 0; _i < 4; _i++) {                                     \
            cp16(_ab + (dsw + _i * 4096), aptr[_i] + _k0);                   \
            cp16(_bb + (dsw + _i * 4096), bptr[_i] + _k0);                   \
        }                                                                    \
    } while (0)
    // note: rows r and r+32 differ by 32*128 bytes; SWZ only mixes bits<7 with
    // bits 7-9 of the row offset... 32*128 = 4096, bits >= 12 unaffected ✓

    ISSUE(0); CP_COMMIT();
    ISSUE(1); CP_COMMIT();

    // ---- compute setup
    int lane = t & 31, wid = t >> 5;
    int wm = wid & 1, wn = wid >> 1;               // 2 x 4 warps
    int arow0 = wm * 64 + (lane & 15);             // + im*16
    int brow0 = wn * 32 + (lane & 15);             // + j*16
    int csel  = (lane >> 4) * 16;                  // 16B column half

    float acc[4][4][4];
    #pragma unroll
    for (int a = 0; a < 4; a++)
        #pragma unroll
        for (int b = 0; b < 4; b++)
            #pragma unroll
            for (int c = 0; c < 4; c++) acc[a][b][c] = 0.f;

    for (int it = 0; it < KITER; it++) {
        CP_WAIT1();
        __syncthreads();
        if (it + 2 < KITER) { ISSUE(it + 2); }
        CP_COMMIT();

        uint32_t ab = sb + (it % PSTAGE) * STAGE_BYTES;
        uint32_t bb = ab + 16384;
        #pragma unroll
        for (int kk = 0; kk < 4; kk++) {
            int colb = kk * 32 + csel;
            uint32_t afr[4][4];
            #pragma unroll
            for (int im = 0; im < 4; im++)
                ldm4(ab + SWZ((arow0 + im * 16) * 128 + colb),
                     afr[im][0], afr[im][1], afr[im][2], afr[im][3]);
            uint32_t bfr[2][4];
            #pragma unroll
            for (int j = 0; j < 2; j++)
                ldm4(bb + SWZ((brow0 + j * 16) * 128 + colb),
                     bfr[j][0], bfr[j][1], bfr[j][2], bfr[j][3]);
            #pragma unroll
            for (int im = 0; im < 4; im++) {
                mma16816(acc[im][0], afr[im], bfr[0][0], bfr[0][2]);
                mma16816(acc[im][1], afr[im], bfr[0][1], bfr[0][3]);
                mma16816(acc[im][2], afr[im], bfr[1][0], bfr[1][2]);
                mma16816(acc[im][3], afr[im], bfr[1][1], bfr[1][3]);
            }
        }
        __syncthreads();
    }

    // ---- epilogue: scale by routing weight, scatter rows
    int qr = lane >> 2, qc = (lane & 3) * 2;
    #pragma unroll
    for (int im = 0; im < 4; im++) {
        #pragma unroll
        for (int p = 0; p < 2; p++) {
            int r = wm * 64 + im * 16 + p * 8 + qr;
            if (m0 + r < cnt) {
                float wt = s_wt[r];
                float* dst = g_buf[s_slot[r]] + (size_t)s_tok[r] * H + n0 + wn * 32 + qc;
                #pragma unroll
                for (int inn = 0; inn < 4; inn++) {
                    float2 v;
                    v.x = acc[im][inn][p * 2 + 0] * wt;
                    v.y = acc[im][inn][p * 2 + 1] * wt;
                    *(float2*)(dst + inn * 8) = v;
                }
            }
        }
    }
}

// ------------------------------------------------------------------ combine
__global__ __launch_bounds__(256) void combine_kernel(float* __restrict__ out) {
    size_t idx = (size_t)blockIdx.x * 256 + threadIdx.x;  // float4 index
    int n = (int)(idx >> 8);
    float4 a = ((const float4*)g_buf[0])[idx];
    float4 b = ((const float4*)g_buf[1])[idx];
    float  c = g_C[n];
    float4 o;
    o.x = a.x + b.x + c;
    o.y = a.y + b.y + c;
    o.z = a.z + b.z + c;
    o.w = a.w + b.w + c;
    ((float4*)out)[idx] = o;
}

// ------------------------------------------------------------------ launch
extern "C" void kernel_launch(void* const* d_in, const int* in_sizes, int n_in,
                              void* d_out, int out_size) {
    const float* x  = (const float*)d_in[0];   // [8192, 1024]
    const float* rw = (const float*)d_in[1];   // [8, 1024]
    const float* W  = (const float*)d_in[2];   // [8, 1024, 1024]
    float* out = (float*)d_out;

    cudaFuncSetAttribute(expert_gemm, cudaFuncAttributeMaxDynamicSharedMemorySize,
                         SMEM_BYTES);

    reset_kernel<<<1, 32>>>();
    convert_x<<<(NTOK * H / 4) / 256, 256>>>(x);
    convert_w<<<dim3(H / 32, H / 32, NEXP), 256>>>(W);
    router_kernel<<<NTOK / 8, 256>>>(x, rw);
    expert_gemm<<<dim3(MAXPE / BM, H / BN, NEXP), 256, SMEM_BYTES>>>();
    combine_kernel<<<(NTOK * H / 4) / 256, 256>>>(out);
}